// round 5
// baseline (speedup 1.0000x reference)
#include <cuda_runtime.h>
#include <cstdint>
#include <math.h>

// Problem constants
#define S_SPANS 16384
#define H_DIM   768
#define K1      2304    // 3*H
#define T_TOK   131072
#define MAXLEN  32

// Scratch (static __device__ arrays: allocation-free per harness rules)
__device__ float g_feat[(size_t)S_SPANS * K1];   // [S, 3H]
__device__ float g_z[(size_t)S_SPANS * H_DIM];   // [S, H]
__device__ int   g_spans_is64;                   // 1 if spans buffer is int64

// ---------------- f32x2 packed-math helpers (sm_100+ PTX) ----------------
__device__ __forceinline__ unsigned long long pack2(float lo, float hi) {
    unsigned long long r;
    asm("mov.b64 %0, {%1, %2};" : "=l"(r) : "f"(lo), "f"(hi));
    return r;
}
__device__ __forceinline__ void unpack2(unsigned long long v, float& lo, float& hi) {
    asm("mov.b64 {%0, %1}, %2;" : "=f"(lo), "=f"(hi) : "l"(v));
}
__device__ __forceinline__ unsigned long long fma2(unsigned long long a,
                                                   unsigned long long b,
                                                   unsigned long long c) {
    unsigned long long d;
    asm("fma.rn.f32x2 %0, %1, %2, %3;" : "=l"(d) : "l"(a), "l"(b), "l"(c));
    return d;
}

__device__ __forceinline__ float gelu_exact(float x) {
    return 0.5f * x * (1.0f + erff(x * 0.70710678118654752f));
}

// ---------------- Kernel 0: spans dtype probe ----------------
// Interpret buffer as int64 span pairs; int32 data read this way fuses
// (start,end) into huge values, so a plausibility check discriminates cleanly.
__global__ void detect_spans_dtype(const void* __restrict__ spans_raw) {
    const long long* s64 = (const long long*)spans_raw;
    const int t = threadIdx.x;  // 32 threads, check 32 spans
    const long long a = s64[2 * t];
    const long long b = s64[2 * t + 1];
    const bool ok = (a >= 0) && (b > a) && (b <= (long long)T_TOK) &&
                    (b - a <= (long long)MAXLEN);
    const unsigned mask = __ballot_sync(0xFFFFFFFFu, ok);
    if (t == 0) g_spans_is64 = (mask == 0xFFFFFFFFu) ? 1 : 0;
}

// ---------------- Kernel 1: span gather -> feat = [h_start | h_end | h_mean] ----------------
// One block per span, 192 threads, one float4 channel-group per thread (768/4 = 192).
__global__ void gather_kernel(const float* __restrict__ emb,
                              const void* __restrict__ spans_raw) {
    const int s   = blockIdx.x;
    const int tid = threadIdx.x;  // 0..191
    int start, end;
    if (g_spans_is64) {
        const long long* sp = (const long long*)spans_raw;
        start = (int)sp[2 * s];
        end   = (int)sp[2 * s + 1];
    } else {
        const int* sp = (const int*)spans_raw;
        start = sp[2 * s];
        end   = sp[2 * s + 1];
    }
    const int len = end - start;

    const float4* e4 = (const float4*)emb;  // 192 float4 per row
    const size_t base = (size_t)start * 192 + tid;

    float4 hs = e4[base];
    float4 he = e4[(size_t)(end - 1) * 192 + tid];

    // Two independent accumulator chains for MLP
    float4 a0 = make_float4(0.f, 0.f, 0.f, 0.f);
    float4 a1 = make_float4(0.f, 0.f, 0.f, 0.f);
    size_t p = base;
    int r = 0;
    for (; r + 1 < len; r += 2) {
        float4 v0 = e4[p];
        float4 v1 = e4[p + 192];
        a0.x += v0.x; a0.y += v0.y; a0.z += v0.z; a0.w += v0.w;
        a1.x += v1.x; a1.y += v1.y; a1.z += v1.z; a1.w += v1.w;
        p += 384;
    }
    if (r < len) {
        float4 v = e4[p];
        a0.x += v.x; a0.y += v.y; a0.z += v.z; a0.w += v.w;
    }
    const float inv = 1.0f / (float)len;
    float4 hm = make_float4((a0.x + a1.x) * inv, (a0.y + a1.y) * inv,
                            (a0.z + a1.z) * inv, (a0.w + a1.w) * inv);

    float4* f4 = (float4*)g_feat;           // 576 float4 per feat row
    const size_t ob = (size_t)s * 576;
    f4[ob + tid]       = hs;
    f4[ob + 192 + tid] = he;
    f4[ob + 384 + tid] = hm;
}

// ---------------- Kernel 2: C = gelu(A[M,K] @ B[K,768] + bias), tiled fp32 w/ FFMA2 ----------
// BM=128, BN=128, BK=16, 256 threads, 8x8 per-thread tile (accumulators packed 2-wide along N).
// Requires: M % 128 == 0, K % 16 == 0, N == 768. All hold here.
__global__ __launch_bounds__(256, 2)
void gemm_bias_gelu(const float* __restrict__ A, const float* __restrict__ B,
                    const float* __restrict__ bias, float* __restrict__ C,
                    int K) {
    const int N = 768;
    __shared__ __align__(16) float As[2][16][128];   // [k][m] (transposed)
    __shared__ __align__(16) float Bs[2][16][128];   // [k][n]

    const int tid = threadIdx.x;
    const int tc  = tid & 15;     // 16 thread-cols
    const int tr  = tid >> 4;     // 16 thread-rows
    const int m0  = blockIdx.y * 128;
    const int n0  = blockIdx.x * 128;

    unsigned long long acc[8][4];
    #pragma unroll
    for (int i = 0; i < 8; i++)
        #pragma unroll
        for (int j = 0; j < 4; j++) acc[i][j] = 0ull;

    const int nk = K >> 4;

    // ---- load tile 0 ----
    #pragma unroll
    for (int pp = 0; pp < 2; pp++) {
        const int i = tid + pp * 256;
        const int row = i >> 2, kq = i & 3;
        float4 v = *(const float4*)&A[(size_t)(m0 + row) * K + kq * 4];
        As[0][kq * 4 + 0][row] = v.x;
        As[0][kq * 4 + 1][row] = v.y;
        As[0][kq * 4 + 2][row] = v.z;
        As[0][kq * 4 + 3][row] = v.w;
        const int kk = i >> 5, nq = i & 31;
        float4 w = *(const float4*)&B[(size_t)kk * N + n0 + nq * 4];
        *(float4*)&Bs[0][kk][nq * 4] = w;
    }
    __syncthreads();

    for (int kt = 0; kt < nk; kt++) {
        const int cur = kt & 1;
        float4 av[2], bv[2];
        const bool more = (kt + 1 < nk);
        if (more) {
            const int k0 = (kt + 1) << 4;
            #pragma unroll
            for (int pp = 0; pp < 2; pp++) {
                const int i = tid + pp * 256;
                const int row = i >> 2, kq = i & 3;
                av[pp] = *(const float4*)&A[(size_t)(m0 + row) * K + k0 + kq * 4];
                const int kk = i >> 5, nq = i & 31;
                bv[pp] = *(const float4*)&B[(size_t)(k0 + kk) * N + n0 + nq * 4];
            }
        }

        #pragma unroll
        for (int k = 0; k < 16; k++) {
            float4 a0 = *(const float4*)&As[cur][k][tr * 4];
            float4 a1 = *(const float4*)&As[cur][k][64 + tr * 4];
            ulonglong2 bq0 = *(const ulonglong2*)&Bs[cur][k][tc * 4];
            ulonglong2 bq1 = *(const ulonglong2*)&Bs[cur][k][64 + tc * 4];
            const float am[8] = {a0.x, a0.y, a0.z, a0.w, a1.x, a1.y, a1.z, a1.w};
            const unsigned long long bp[4] = {bq0.x, bq0.y, bq1.x, bq1.y};
            #pragma unroll
            for (int i = 0; i < 8; i++) {
                const unsigned long long ap = pack2(am[i], am[i]);
                #pragma unroll
                for (int j = 0; j < 4; j++)
                    acc[i][j] = fma2(ap, bp[j], acc[i][j]);
            }
        }

        if (more) {
            const int nxt = cur ^ 1;
            #pragma unroll
            for (int pp = 0; pp < 2; pp++) {
                const int i = tid + pp * 256;
                const int row = i >> 2, kq = i & 3;
                As[nxt][kq * 4 + 0][row] = av[pp].x;
                As[nxt][kq * 4 + 1][row] = av[pp].y;
                As[nxt][kq * 4 + 2][row] = av[pp].z;
                As[nxt][kq * 4 + 3][row] = av[pp].w;
                const int kk = i >> 5, nq = i & 31;
                *(float4*)&Bs[nxt][kk][nq * 4] = bv[pp];
            }
            __syncthreads();
        }
    }

    // ---- epilogue: bias + exact GELU + coalesced float4 stores ----
    float bvals[8];
    #pragma unroll
    for (int jh = 0; jh < 2; jh++) {
        float4 bb = *(const float4*)&bias[n0 + jh * 64 + tc * 4];
        bvals[jh * 4 + 0] = bb.x; bvals[jh * 4 + 1] = bb.y;
        bvals[jh * 4 + 2] = bb.z; bvals[jh * 4 + 3] = bb.w;
    }
    #pragma unroll
    for (int i = 0; i < 8; i++) {
        const int m = m0 + ((i < 4) ? (tr * 4 + i) : (64 + tr * 4 + (i - 4)));
        #pragma unroll
        for (int jh = 0; jh < 2; jh++) {
            float lo0, hi0, lo1, hi1;
            unpack2(acc[i][jh * 2 + 0], lo0, hi0);
            unpack2(acc[i][jh * 2 + 1], lo1, hi1);
            float4 o;
            o.x = gelu_exact(lo0 + bvals[jh * 4 + 0]);
            o.y = gelu_exact(hi0 + bvals[jh * 4 + 1]);
            o.z = gelu_exact(lo1 + bvals[jh * 4 + 2]);
            o.w = gelu_exact(hi1 + bvals[jh * 4 + 3]);
            *(float4*)&C[(size_t)m * N + n0 + jh * 64 + tc * 4] = o;
        }
    }
}

// ---------------- launch ----------------
extern "C" void kernel_launch(void* const* d_in, const int* in_sizes, int n_in,
                              void* d_out, int out_size) {
    const float* emb   = (const float*)d_in[0];
    const void*  spans = d_in[1];                 // int32 or int64; probed on device
    const float* W1    = (const float*)d_in[2];
    const float* b1    = (const float*)d_in[3];
    const float* W2    = (const float*)d_in[4];
    const float* b2    = (const float*)d_in[5];
    float*       out   = (float*)d_out;

    float *feat_ptr = nullptr, *z_ptr = nullptr;
    cudaGetSymbolAddress((void**)&feat_ptr, g_feat);
    cudaGetSymbolAddress((void**)&z_ptr, g_z);

    // 0) determine spans dtype on-device (graph-capturable, deterministic)
    detect_spans_dtype<<<1, 32>>>(spans);
    // 1) feature build
    gather_kernel<<<S_SPANS, 192>>>(emb, spans);
    // 2) z = gelu(feat @ W1 + b1)   [16384,2304]x[2304,768]
    gemm_bias_gelu<<<dim3(H_DIM / 128, S_SPANS / 128), 256>>>(feat_ptr, W1, b1, z_ptr, K1);
    // 3) out = gelu(z @ W2 + b2)    [16384,768]x[768,768]
    gemm_bias_gelu<<<dim3(H_DIM / 128, S_SPANS / 128), 256>>>(z_ptr, W2, b2, out, H_DIM);
}

// round 6
// speedup vs baseline: 1.0010x; 1.0010x over previous
#include <cuda_runtime.h>
#include <cstdint>
#include <math.h>

// Problem constants
#define S_SPANS 16384
#define H_DIM   768
#define K1      2304    // 3*H
#define T_TOK   131072
#define MAXLEN  32

// Scratch (static __device__ arrays: allocation-free per harness rules)
__device__ float g_feat[(size_t)S_SPANS * K1];   // [S, 3H]
__device__ float g_z[(size_t)S_SPANS * H_DIM];   // [S, H]
__device__ int   g_spans_is64;                   // 1 if spans buffer is int64

// ---------------- f32x2 packed-math helpers (sm_100+ PTX) ----------------
__device__ __forceinline__ unsigned long long pack2(float lo, float hi) {
    unsigned long long r;
    asm("mov.b64 %0, {%1, %2};" : "=l"(r) : "f"(lo), "f"(hi));
    return r;
}
__device__ __forceinline__ void unpack2(unsigned long long v, float& lo, float& hi) {
    asm("mov.b64 {%0, %1}, %2;" : "=f"(lo), "=f"(hi) : "l"(v));
}
__device__ __forceinline__ unsigned long long fma2(unsigned long long a,
                                                   unsigned long long b,
                                                   unsigned long long c) {
    unsigned long long d;
    asm("fma.rn.f32x2 %0, %1, %2, %3;" : "=l"(d) : "l"(a), "l"(b), "l"(c));
    return d;
}

__device__ __forceinline__ float gelu_exact(float x) {
    return 0.5f * x * (1.0f + erff(x * 0.70710678118654752f));
}

// ---------------- Kernel 0: spans dtype probe ----------------
// Interpret buffer as int64 span pairs; int32 data read this way fuses
// (start,end) into huge values, so a plausibility check discriminates cleanly.
__global__ void detect_spans_dtype(const void* __restrict__ spans_raw) {
    const long long* s64 = (const long long*)spans_raw;
    const int t = threadIdx.x;  // 32 threads, check 32 spans
    const long long a = s64[2 * t];
    const long long b = s64[2 * t + 1];
    const bool ok = (a >= 0) && (b > a) && (b <= (long long)T_TOK) &&
                    (b - a <= (long long)MAXLEN);
    const unsigned mask = __ballot_sync(0xFFFFFFFFu, ok);
    if (t == 0) g_spans_is64 = (mask == 0xFFFFFFFFu) ? 1 : 0;
}

// ---------------- Kernel 1: span gather -> feat = [h_start | h_end | h_mean] ----------------
// One block per span, 192 threads, one float4 channel-group per thread (768/4 = 192).
__global__ void gather_kernel(const float* __restrict__ emb,
                              const void* __restrict__ spans_raw) {
    const int s   = blockIdx.x;
    const int tid = threadIdx.x;  // 0..191
    int start, end;
    if (g_spans_is64) {
        const long long* sp = (const long long*)spans_raw;
        start = (int)sp[2 * s];
        end   = (int)sp[2 * s + 1];
    } else {
        const int* sp = (const int*)spans_raw;
        start = sp[2 * s];
        end   = sp[2 * s + 1];
    }
    const int len = end - start;

    const float4* e4 = (const float4*)emb;  // 192 float4 per row
    const size_t base = (size_t)start * 192 + tid;

    float4 hs = e4[base];
    float4 he = e4[(size_t)(end - 1) * 192 + tid];

    // Two independent accumulator chains for MLP
    float4 a0 = make_float4(0.f, 0.f, 0.f, 0.f);
    float4 a1 = make_float4(0.f, 0.f, 0.f, 0.f);
    size_t p = base;
    int r = 0;
    for (; r + 1 < len; r += 2) {
        float4 v0 = e4[p];
        float4 v1 = e4[p + 192];
        a0.x += v0.x; a0.y += v0.y; a0.z += v0.z; a0.w += v0.w;
        a1.x += v1.x; a1.y += v1.y; a1.z += v1.z; a1.w += v1.w;
        p += 384;
    }
    if (r < len) {
        float4 v = e4[p];
        a0.x += v.x; a0.y += v.y; a0.z += v.z; a0.w += v.w;
    }
    const float inv = 1.0f / (float)len;
    float4 hm = make_float4((a0.x + a1.x) * inv, (a0.y + a1.y) * inv,
                            (a0.z + a1.z) * inv, (a0.w + a1.w) * inv);

    float4* f4 = (float4*)g_feat;           // 576 float4 per feat row
    const size_t ob = (size_t)s * 576;
    f4[ob + tid]       = hs;
    f4[ob + 192 + tid] = he;
    f4[ob + 384 + tid] = hm;
}

// ---------------- Kernel 2: C = gelu(A[M,K] @ B[K,768] + bias), tiled fp32 w/ FFMA2 ----------
// BM=128, BN=128, BK=16, 256 threads, 8x8 per-thread tile (accumulators packed 2-wide along N).
// Requires: M % 128 == 0, K % 16 == 0, N == 768. All hold here.
__global__ __launch_bounds__(256, 2)
void gemm_bias_gelu(const float* __restrict__ A, const float* __restrict__ B,
                    const float* __restrict__ bias, float* __restrict__ C,
                    int K) {
    const int N = 768;
    __shared__ __align__(16) float As[2][16][128];   // [k][m] (transposed)
    __shared__ __align__(16) float Bs[2][16][128];   // [k][n]

    const int tid = threadIdx.x;
    const int tc  = tid & 15;     // 16 thread-cols
    const int tr  = tid >> 4;     // 16 thread-rows
    const int m0  = blockIdx.y * 128;
    const int n0  = blockIdx.x * 128;

    unsigned long long acc[8][4];
    #pragma unroll
    for (int i = 0; i < 8; i++)
        #pragma unroll
        for (int j = 0; j < 4; j++) acc[i][j] = 0ull;

    const int nk = K >> 4;

    // ---- load tile 0 ----
    #pragma unroll
    for (int pp = 0; pp < 2; pp++) {
        const int i = tid + pp * 256;
        const int row = i >> 2, kq = i & 3;
        float4 v = *(const float4*)&A[(size_t)(m0 + row) * K + kq * 4];
        As[0][kq * 4 + 0][row] = v.x;
        As[0][kq * 4 + 1][row] = v.y;
        As[0][kq * 4 + 2][row] = v.z;
        As[0][kq * 4 + 3][row] = v.w;
        const int kk = i >> 5, nq = i & 31;
        float4 w = *(const float4*)&B[(size_t)kk * N + n0 + nq * 4];
        *(float4*)&Bs[0][kk][nq * 4] = w;
    }
    __syncthreads();

    for (int kt = 0; kt < nk; kt++) {
        const int cur = kt & 1;
        float4 av[2], bv[2];
        const bool more = (kt + 1 < nk);
        if (more) {
            const int k0 = (kt + 1) << 4;
            #pragma unroll
            for (int pp = 0; pp < 2; pp++) {
                const int i = tid + pp * 256;
                const int row = i >> 2, kq = i & 3;
                av[pp] = *(const float4*)&A[(size_t)(m0 + row) * K + k0 + kq * 4];
                const int kk = i >> 5, nq = i & 31;
                bv[pp] = *(const float4*)&B[(size_t)(k0 + kk) * N + n0 + nq * 4];
            }
        }

        #pragma unroll
        for (int k = 0; k < 16; k++) {
            float4 a0 = *(const float4*)&As[cur][k][tr * 4];
            float4 a1 = *(const float4*)&As[cur][k][64 + tr * 4];
            ulonglong2 bq0 = *(const ulonglong2*)&Bs[cur][k][tc * 4];
            ulonglong2 bq1 = *(const ulonglong2*)&Bs[cur][k][64 + tc * 4];
            const float am[8] = {a0.x, a0.y, a0.z, a0.w, a1.x, a1.y, a1.z, a1.w};
            const unsigned long long bp[4] = {bq0.x, bq0.y, bq1.x, bq1.y};
            #pragma unroll
            for (int i = 0; i < 8; i++) {
                const unsigned long long ap = pack2(am[i], am[i]);
                #pragma unroll
                for (int j = 0; j < 4; j++)
                    acc[i][j] = fma2(ap, bp[j], acc[i][j]);
            }
        }

        if (more) {
            const int nxt = cur ^ 1;
            #pragma unroll
            for (int pp = 0; pp < 2; pp++) {
                const int i = tid + pp * 256;
                const int row = i >> 2, kq = i & 3;
                As[nxt][kq * 4 + 0][row] = av[pp].x;
                As[nxt][kq * 4 + 1][row] = av[pp].y;
                As[nxt][kq * 4 + 2][row] = av[pp].z;
                As[nxt][kq * 4 + 3][row] = av[pp].w;
                const int kk = i >> 5, nq = i & 31;
                *(float4*)&Bs[nxt][kk][nq * 4] = bv[pp];
            }
            __syncthreads();
        }
    }

    // ---- epilogue: bias + exact GELU + coalesced float4 stores ----
    float bvals[8];
    #pragma unroll
    for (int jh = 0; jh < 2; jh++) {
        float4 bb = *(const float4*)&bias[n0 + jh * 64 + tc * 4];
        bvals[jh * 4 + 0] = bb.x; bvals[jh * 4 + 1] = bb.y;
        bvals[jh * 4 + 2] = bb.z; bvals[jh * 4 + 3] = bb.w;
    }
    #pragma unroll
    for (int i = 0; i < 8; i++) {
        const int m = m0 + ((i < 4) ? (tr * 4 + i) : (64 + tr * 4 + (i - 4)));
        #pragma unroll
        for (int jh = 0; jh < 2; jh++) {
            float lo0, hi0, lo1, hi1;
            unpack2(acc[i][jh * 2 + 0], lo0, hi0);
            unpack2(acc[i][jh * 2 + 1], lo1, hi1);
            float4 o;
            o.x = gelu_exact(lo0 + bvals[jh * 4 + 0]);
            o.y = gelu_exact(hi0 + bvals[jh * 4 + 1]);
            o.z = gelu_exact(lo1 + bvals[jh * 4 + 2]);
            o.w = gelu_exact(hi1 + bvals[jh * 4 + 3]);
            *(float4*)&C[(size_t)m * N + n0 + jh * 64 + tc * 4] = o;
        }
    }
}

// ---------------- launch ----------------
extern "C" void kernel_launch(void* const* d_in, const int* in_sizes, int n_in,
                              void* d_out, int out_size) {
    const float* emb   = (const float*)d_in[0];
    const void*  spans = d_in[1];                 // int32 or int64; probed on device
    const float* W1    = (const float*)d_in[2];
    const float* b1    = (const float*)d_in[3];
    const float* W2    = (const float*)d_in[4];
    const float* b2    = (const float*)d_in[5];
    float*       out   = (float*)d_out;

    float *feat_ptr = nullptr, *z_ptr = nullptr;
    cudaGetSymbolAddress((void**)&feat_ptr, g_feat);
    cudaGetSymbolAddress((void**)&z_ptr, g_z);

    // 0) determine spans dtype on-device (graph-capturable, deterministic)
    detect_spans_dtype<<<1, 32>>>(spans);
    // 1) feature build
    gather_kernel<<<S_SPANS, 192>>>(emb, spans);
    // 2) z = gelu(feat @ W1 + b1)   [16384,2304]x[2304,768]
    gemm_bias_gelu<<<dim3(H_DIM / 128, S_SPANS / 128), 256>>>(feat_ptr, W1, b1, z_ptr, K1);
    // 3) out = gelu(z @ W2 + b2)    [16384,768]x[768,768]
    gemm_bias_gelu<<<dim3(H_DIM / 128, S_SPANS / 128), 256>>>(z_ptr, W2, b2, out, H_DIM);
}